// round 3
// baseline (speedup 1.0000x reference)
#include <cuda_runtime.h>

#define Bsz 32
#define Hh 480
#define Ww 640
#define HW (Hh*Ww)          // 307200 pixels per channel-plane
#define HW4 (HW/4)          // 76800 float4 per plane
#define RED_BLOCKS 300      // 76800 / 256

__device__ float d_gray_sum[Bsz];

__global__ void zero_sums() {
    if (threadIdx.x < Bsz) d_gray_sum[threadIdx.x] = 0.0f;
}

__device__ __forceinline__ float clip01(float v) {
    return fminf(fmaxf(v, 0.0f), 1.0f);
}

// Pass 1: per-batch sum of gray(clip(x * bf)).  grid = (RED_BLOCKS, B), block = 256
__global__ void gray_reduce(const float* __restrict__ x,
                            const float* __restrict__ bf) {
    const int b   = blockIdx.y;
    const int g4  = blockIdx.x * blockDim.x + threadIdx.x;   // float4 index in plane
    const float s = bf[b];

    const float4* base = (const float4*)(x) + (size_t)b * 3 * HW4;
    float4 r4 = base[g4];
    float4 g4v = base[g4 + HW4];
    float4 b4 = base[g4 + 2 * HW4];

    float acc = 0.0f;
    {
        float r = clip01(r4.x * s), g = clip01(g4v.x * s), bb = clip01(b4.x * s);
        acc += 0.299f * r + 0.587f * g + 0.114f * bb;
        r = clip01(r4.y * s); g = clip01(g4v.y * s); bb = clip01(b4.y * s);
        acc += 0.299f * r + 0.587f * g + 0.114f * bb;
        r = clip01(r4.z * s); g = clip01(g4v.z * s); bb = clip01(b4.z * s);
        acc += 0.299f * r + 0.587f * g + 0.114f * bb;
        r = clip01(r4.w * s); g = clip01(g4v.w * s); bb = clip01(b4.w * s);
        acc += 0.299f * r + 0.587f * g + 0.114f * bb;
    }

    // warp reduce
    for (int off = 16; off > 0; off >>= 1)
        acc += __shfl_down_sync(0xFFFFFFFF, acc, off);

    __shared__ float warp_part[8];
    int lane = threadIdx.x & 31;
    int wid  = threadIdx.x >> 5;
    if (lane == 0) warp_part[wid] = acc;
    __syncthreads();
    if (wid == 0) {
        float v = (lane < 8) ? warp_part[lane] : 0.0f;
        for (int off = 4; off > 0; off >>= 1)
            v += __shfl_down_sync(0xFFFFFFFF, v, off);
        if (lane == 0) atomicAdd(&d_gray_sum[b], v);
    }
}

// Pass 2: fused brightness/contrast/saturation/hue.  One thread = 4 pixels (all 3 ch).
__global__ void color_xform(const float* __restrict__ x,
                            const float* __restrict__ bfv,
                            const float* __restrict__ cfv,
                            const float* __restrict__ sfv,
                            const float* __restrict__ hfv,
                            float* __restrict__ out) {
    const int idx = blockIdx.x * blockDim.x + threadIdx.x;   // 0 .. B*HW4-1
    const int b   = idx / HW4;
    const int g4  = idx - b * HW4;

    const float bf = bfv[b];
    const float cf = cfv[b];
    const float sf = sfv[b];
    const float hf = hfv[b];
    const float mean = d_gray_sum[b] * (1.0f / (float)HW);

    const float4* ibase = (const float4*)(x)   + (size_t)b * 3 * HW4;
    float4*       obase = (float4*)(out)       + (size_t)b * 3 * HW4;

    float4 rv = ibase[g4];
    float4 gv = ibase[g4 + HW4];
    float4 bv = ibase[g4 + 2 * HW4];

    float rr[4] = {rv.x, rv.y, rv.z, rv.w};
    float gg[4] = {gv.x, gv.y, gv.z, gv.w};
    float bb[4] = {bv.x, bv.y, bv.z, bv.w};

    #pragma unroll
    for (int k = 0; k < 4; k++) {
        // brightness
        float r = clip01(rr[k] * bf);
        float g = clip01(gg[k] * bf);
        float bl = clip01(bb[k] * bf);
        // contrast (blend with per-batch mean)
        r = clip01(cf * r + (1.0f - cf) * mean);
        g = clip01(cf * g + (1.0f - cf) * mean);
        bl = clip01(cf * bl + (1.0f - cf) * mean);
        // saturation (blend with per-pixel gray)
        float gray = 0.299f * r + 0.587f * g + 0.114f * bl;
        r = clip01(sf * r + (1.0f - sf) * gray);
        g = clip01(sf * g + (1.0f - sf) * gray);
        bl = clip01(sf * bl + (1.0f - sf) * gray);
        // hue: rgb -> hsv-ish -> rotate -> rgb
        float maxc = fmaxf(r, fmaxf(g, bl));
        float minc = fminf(r, fminf(g, bl));
        float v = maxc;
        float cr = maxc - minc;
        float crd = (cr == 0.0f) ? 1.0f : cr;
        float s = cr / ((maxc == 0.0f) ? 1.0f : maxc);
        float inv_crd = 1.0f / crd;
        float rc = (maxc - r) * inv_crd;
        float gc = (maxc - g) * inv_crd;
        float bc = (maxc - bl) * inv_crd;
        float hh;
        if (maxc == r)       hh = bc - gc;
        else if (maxc == g)  hh = 2.0f + rc - bc;
        else                 hh = 4.0f + gc - rc;
        float h = hh * (1.0f / 6.0f);
        h = h - floorf(h);          // % 1.0 (floor-mod)
        h = h + hf;
        h = h - floorf(h);
        float i6 = h * 6.0f;
        float fi = floorf(i6);
        float f  = i6 - fi;
        int i = ((int)fi) % 6;
        float p = v * (1.0f - s);
        float q = v * (1.0f - f * s);
        float t = v * (1.0f - (1.0f - f) * s);
        float r2, g2, b2;
        switch (i) {
            case 0: r2 = v; g2 = t; b2 = p; break;
            case 1: r2 = q; g2 = v; b2 = p; break;
            case 2: r2 = p; g2 = v; b2 = t; break;
            case 3: r2 = p; g2 = q; b2 = v; break;
            case 4: r2 = t; g2 = p; b2 = v; break;
            default: r2 = v; g2 = p; b2 = q; break;
        }
        rr[k] = r2; gg[k] = g2; bb[k] = b2;
    }

    obase[g4]           = make_float4(rr[0], rr[1], rr[2], rr[3]);
    obase[g4 + HW4]     = make_float4(gg[0], gg[1], gg[2], gg[3]);
    obase[g4 + 2 * HW4] = make_float4(bb[0], bb[1], bb[2], bb[3]);
}

extern "C" void kernel_launch(void* const* d_in, const int* in_sizes, int n_in,
                              void* d_out, int out_size) {
    const float* x  = (const float*)d_in[0];
    const float* bf = (const float*)d_in[1];
    const float* cf = (const float*)d_in[2];
    const float* sf = (const float*)d_in[3];
    const float* hf = (const float*)d_in[4];
    float* out = (float*)d_out;

    zero_sums<<<1, 32>>>();
    gray_reduce<<<dim3(RED_BLOCKS, Bsz), 256>>>(x, bf);
    color_xform<<<(Bsz * HW4) / 256, 256>>>(x, bf, cf, sf, hf, out);
}

// round 5
// speedup vs baseline: 1.0248x; 1.0248x over previous
#include <cuda_runtime.h>

#define Bsz 32
#define Hh 480
#define Ww 640
#define HW (Hh*Ww)          // 307200 pixels per channel-plane
#define HW4 (HW/4)          // 76800 float4 per plane
#define RED_BLOCKS 300      // 76800 / 256

__device__ float d_gray_sum[Bsz];

__global__ void zero_sums() {
    if (threadIdx.x < Bsz) d_gray_sum[threadIdx.x] = 0.0f;
}

__device__ __forceinline__ float clip01(float v) {
    return fminf(fmaxf(v, 0.0f), 1.0f);
}

// Pass 1: per-batch sum of gray(clip(x * bf)).  grid = (RED_BLOCKS, B), block = 256
// Default load policy: leave input resident in L2 for pass 2.
__global__ void __launch_bounds__(256) gray_reduce(const float* __restrict__ x,
                                                   const float* __restrict__ bf) {
    const int b   = blockIdx.y;
    const int g4  = blockIdx.x * blockDim.x + threadIdx.x;   // float4 index in plane
    const float s = bf[b];

    const float4* base = (const float4*)(x) + (size_t)b * 3 * HW4;
    float4 r4 = base[g4];
    float4 g4v = base[g4 + HW4];
    float4 b4 = base[g4 + 2 * HW4];

    float acc = 0.0f;
    {
        float r = clip01(r4.x * s), g = clip01(g4v.x * s), bb = clip01(b4.x * s);
        acc += 0.299f * r + 0.587f * g + 0.114f * bb;
        r = clip01(r4.y * s); g = clip01(g4v.y * s); bb = clip01(b4.y * s);
        acc += 0.299f * r + 0.587f * g + 0.114f * bb;
        r = clip01(r4.z * s); g = clip01(g4v.z * s); bb = clip01(b4.z * s);
        acc += 0.299f * r + 0.587f * g + 0.114f * bb;
        r = clip01(r4.w * s); g = clip01(g4v.w * s); bb = clip01(b4.w * s);
        acc += 0.299f * r + 0.587f * g + 0.114f * bb;
    }

    // warp reduce
    for (int off = 16; off > 0; off >>= 1)
        acc += __shfl_down_sync(0xFFFFFFFF, acc, off);

    __shared__ float warp_part[8];
    int lane = threadIdx.x & 31;
    int wid  = threadIdx.x >> 5;
    if (lane == 0) warp_part[wid] = acc;
    __syncthreads();
    if (wid == 0) {
        float v = (lane < 8) ? warp_part[lane] : 0.0f;
        for (int off = 4; off > 0; off >>= 1)
            v += __shfl_down_sync(0xFFFFFFFF, v, off);
        if (lane == 0) atomicAdd(&d_gray_sum[b], v);
    }
}

// Pass 2: fused brightness/contrast/saturation/hue.  One thread = 4 pixels (all 3 ch).
// Loads: __ldcs (last use, evict-first).  Stores: __stcs (streaming, don't pollute L2).
__global__ void __launch_bounds__(256) color_xform(const float* __restrict__ x,
                            const float* __restrict__ bfv,
                            const float* __restrict__ cfv,
                            const float* __restrict__ sfv,
                            const float* __restrict__ hfv,
                            float* __restrict__ out) {
    const int idx = blockIdx.x * blockDim.x + threadIdx.x;   // 0 .. B*HW4-1
    const int b   = idx / HW4;
    const int g4  = idx - b * HW4;

    const float bf = bfv[b];
    const float cf = cfv[b];
    const float sf = sfv[b];
    const float hf = hfv[b];
    const float mean = d_gray_sum[b] * (1.0f / (float)HW);

    const float4* ibase = (const float4*)(x)   + (size_t)b * 3 * HW4;
    float4*       obase = (float4*)(out)       + (size_t)b * 3 * HW4;

    float4 rv = __ldcs(ibase + g4);
    float4 gv = __ldcs(ibase + g4 + HW4);
    float4 bv = __ldcs(ibase + g4 + 2 * HW4);

    float rr[4] = {rv.x, rv.y, rv.z, rv.w};
    float gg[4] = {gv.x, gv.y, gv.z, gv.w};
    float bb[4] = {bv.x, bv.y, bv.z, bv.w};

    #pragma unroll
    for (int k = 0; k < 4; k++) {
        // brightness
        float r = clip01(rr[k] * bf);
        float g = clip01(gg[k] * bf);
        float bl = clip01(bb[k] * bf);
        // contrast (blend with per-batch mean)
        r = clip01(cf * r + (1.0f - cf) * mean);
        g = clip01(cf * g + (1.0f - cf) * mean);
        bl = clip01(cf * bl + (1.0f - cf) * mean);
        // saturation (blend with per-pixel gray)
        float gray = 0.299f * r + 0.587f * g + 0.114f * bl;
        r = clip01(sf * r + (1.0f - sf) * gray);
        g = clip01(sf * g + (1.0f - sf) * gray);
        bl = clip01(sf * bl + (1.0f - sf) * gray);
        // hue: rgb -> hsv-ish -> rotate -> rgb
        float maxc = fmaxf(r, fmaxf(g, bl));
        float minc = fminf(r, fminf(g, bl));
        float v = maxc;
        float cr = maxc - minc;
        float crd = (cr == 0.0f) ? 1.0f : cr;
        float s = cr / ((maxc == 0.0f) ? 1.0f : maxc);
        float inv_crd = 1.0f / crd;
        float rc = (maxc - r) * inv_crd;
        float gc = (maxc - g) * inv_crd;
        float bc = (maxc - bl) * inv_crd;
        float hh;
        if (maxc == r)       hh = bc - gc;
        else if (maxc == g)  hh = 2.0f + rc - bc;
        else                 hh = 4.0f + gc - rc;
        float h = hh * (1.0f / 6.0f);
        h = h - floorf(h);          // % 1.0 (floor-mod)
        h = h + hf;
        h = h - floorf(h);
        float i6 = h * 6.0f;
        float fi = floorf(i6);
        float f  = i6 - fi;
        int i = ((int)fi) % 6;
        float p = v * (1.0f - s);
        float q = v * (1.0f - f * s);
        float t = v * (1.0f - (1.0f - f) * s);
        float r2, g2, b2;
        switch (i) {
            case 0: r2 = v; g2 = t; b2 = p; break;
            case 1: r2 = q; g2 = v; b2 = p; break;
            case 2: r2 = p; g2 = v; b2 = t; break;
            case 3: r2 = p; g2 = q; b2 = v; break;
            case 4: r2 = t; g2 = p; b2 = v; break;
            default: r2 = v; g2 = p; b2 = q; break;
        }
        rr[k] = r2; gg[k] = g2; bb[k] = b2;
    }

    __stcs(obase + g4,           make_float4(rr[0], rr[1], rr[2], rr[3]));
    __stcs(obase + g4 + HW4,     make_float4(gg[0], gg[1], gg[2], gg[3]));
    __stcs(obase + g4 + 2 * HW4, make_float4(bb[0], bb[1], bb[2], bb[3]));
}

extern "C" void kernel_launch(void* const* d_in, const int* in_sizes, int n_in,
                              void* d_out, int out_size) {
    const float* x  = (const float*)d_in[0];
    const float* bf = (const float*)d_in[1];
    const float* cf = (const float*)d_in[2];
    const float* sf = (const float*)d_in[3];
    const float* hf = (const float*)d_in[4];
    float* out = (float*)d_out;

    zero_sums<<<1, 32>>>();
    gray_reduce<<<dim3(RED_BLOCKS, Bsz), 256>>>(x, bf);
    color_xform<<<(Bsz * HW4) / 256, 256>>>(x, bf, cf, sf, hf, out);
}